// round 7
// baseline (speedup 1.0000x reference)
#include <cuda_runtime.h>

#define NN 100000   // nodes
#define NE 500000   // edges
#define NH 4        // heads
#define HD 32       // output width
#define PROJ 128
#define U16 16      // folded edge-feature width

#define GRID_BLOCKS 512
#define BLOCK_THREADS 256

// folded-parameter layout inside g_fold (floats)
#define A_OFF     0            // 4*3*3 = 36  quadratic form (pre-scaled 1/sqrt(32))
#define LIN_OFF   36           // 4*3  = 12
#define S0_OFF    48           // 4
#define SCORE_SZ  52
#define B_OFF     52           // 16*32 = 512
#define BOUT_OFF  564          // 32
#define GAMMA_OFF 596          // 32
#define BETA_OFF  628          // 32
#define FOLD_SZ   660

// ---------------- device scratch (no allocations allowed) ----------------
// g_seg starts zeroed (static init) and is re-zeroed by the node phase every
// launch after it consumes the values, so each edge phase sees zeros.
__device__ __align__(16) float g_seg[NN * U16];
__device__ __align__(16) float4 g_pos4[NN];      // padded positions for 1-LDG gathers
__device__ __align__(16) float g_fold[FOLD_SZ];  // folded params
__device__ int   g_is64;                         // edge_index dtype flag

// grid-barrier state: counters reset by the releasing block each use;
// release flags increase monotonically across graph replays (wrap-safe).
__device__ unsigned g_barcnt[2];
__device__ volatile unsigned g_barrel[2];

__device__ __forceinline__ void grid_bar(int id) {
    __syncthreads();
    if (threadIdx.x == 0) {
        unsigned old = g_barrel[id];
        __threadfence();                       // make this block's writes visible
        unsigned prev = atomicAdd(&g_barcnt[id], 1u);
        if (prev == GRID_BLOCKS - 1) {
            g_barcnt[id] = 0;                  // reset for next launch
            __threadfence();
            g_barrel[id] = old + 1u;           // release
        } else {
            while (g_barrel[id] == old) { }    // HW-coherent L2 poll
            __threadfence();                   // acquire
        }
    }
    __syncthreads();
}

// ---------------- edge helper ----------------
__device__ __forceinline__ void red_add_v4(float* p, float4 v) {
    asm volatile("red.global.add.v4.f32 [%0], {%1,%2,%3,%4};"
                 :: "l"(p), "f"(v.x), "f"(v.y), "f"(v.z), "f"(v.w)
                 : "memory");
}

__device__ __forceinline__ void edge_compute(const float* sp, int col, float4 pr, float4 pc) {
    float r[3] = { pr.x - pc.x, pr.y - pc.y, pr.z - pc.z };
    float s[NH];
    float mx = -1e30f;
#pragma unroll
    for (int h = 0; h < NH; h++) {
        float acc = sp[S0_OFF + h];
#pragma unroll
        for (int i = 0; i < 3; i++) {
            float t = sp[LIN_OFF + h * 3 + i];
#pragma unroll
            for (int j = 0; j < 3; j++)
                t = fmaf(sp[A_OFF + h * 9 + i * 3 + j], r[j], t);
            acc = fmaf(r[i], t, acc);
        }
        s[h] = acc;
        mx = fmaxf(mx, acc);
    }
    float a[NH], den = 0.f;
#pragma unroll
    for (int h = 0; h < NH; h++) { a[h] = __expf(s[h] - mx); den += a[h]; }
    float dinv = 1.0f / den;

    float* base = &g_seg[(size_t)col * U16];
#pragma unroll
    for (int h = 0; h < NH; h++) {
        float ah = a[h] * dinv;
        red_add_v4(base + h * 4, make_float4(ah * r[0], ah * r[1], ah * r[2], ah));
    }
}

// ---------------- the one fused kernel ----------------
__global__ void __launch_bounds__(BLOCK_THREADS, 4) fused_kernel(
        const float* __restrict__ pos,
        const int* __restrict__ eraw,
        const float* __restrict__ Wq, const float* __restrict__ bq,
        const float* __restrict__ Wk, const float* __restrict__ bk,
        const float* __restrict__ Wv, const float* __restrict__ bv,
        const float* __restrict__ Wout, const float* __restrict__ bout,
        const float* __restrict__ gamma, const float* __restrict__ beta,
        float* __restrict__ out) {
    __shared__ __align__(16) float sp[SCORE_SZ];     // edge-phase score params
    __shared__ __align__(16) float sB[U16 * HD];     // node-phase B matrix
    __shared__ __align__(16) float sEpi[3 * HD];     // bout | gamma | beta

    const int t   = threadIdx.x;
    const int gid = blockIdx.x * BLOCK_THREADS + t;
    const int gsz = GRID_BLOCKS * BLOCK_THREADS;     // 131072

    // ================= phase 0: pack positions + fold weights =================
    for (int j = gid; j < NN; j += gsz)
        g_pos4[j] = make_float4(__ldg(&pos[j * 3 + 0]),
                                __ldg(&pos[j * 3 + 1]),
                                __ldg(&pos[j * 3 + 2]), 0.f);

    const float inv = 0.17677669529663687f;  // 1/sqrt(32)
    if (blockIdx.x < 2) {
        // B fold: one thread per output, lane = o (coalesced Wout rows)
        int idx = blockIdx.x * BLOCK_THREADS + t;    // 0..511
        int j = idx >> 5, o = idx & 31;
        int h = j >> 2, ii = j & 3;
        const float* wsrc = (ii < 3) ? &Wv[ii * PROJ + h * HD] : &bv[h * HD];
        const float* wo   = &Wout[(size_t)h * HD * HD + o];
        float a0 = 0.f, a1 = 0.f, a2 = 0.f, a3 = 0.f;
#pragma unroll
        for (int d = 0; d < HD; d += 4) {
            a0 = fmaf(__ldg(&wsrc[d + 0]), __ldg(&wo[(d + 0) * HD]), a0);
            a1 = fmaf(__ldg(&wsrc[d + 1]), __ldg(&wo[(d + 1) * HD]), a1);
            a2 = fmaf(__ldg(&wsrc[d + 2]), __ldg(&wo[(d + 2) * HD]), a2);
            a3 = fmaf(__ldg(&wsrc[d + 3]), __ldg(&wo[(d + 3) * HD]), a3);
        }
        g_fold[B_OFF + idx] = (a0 + a1) + (a2 + a3);
    } else if (blockIdx.x == 2) {
        if (t < NH * 9) {
            // A_h[i][j] = sum_d Wq[i, h*32+d] * Wk[j, h*32+d]   (scaled)
            int h = t / 9, ii = (t % 9) / 3, jj = t % 3;
            const float* wq = &Wq[ii * PROJ + h * HD];
            const float* wk = &Wk[jj * PROJ + h * HD];
            float a0 = 0.f, a1 = 0.f, a2 = 0.f, a3 = 0.f;
#pragma unroll
            for (int d = 0; d < HD; d += 4) {
                a0 = fmaf(__ldg(&wq[d + 0]), __ldg(&wk[d + 0]), a0);
                a1 = fmaf(__ldg(&wq[d + 1]), __ldg(&wk[d + 1]), a1);
                a2 = fmaf(__ldg(&wq[d + 2]), __ldg(&wk[d + 2]), a2);
                a3 = fmaf(__ldg(&wq[d + 3]), __ldg(&wk[d + 3]), a3);
            }
            g_fold[A_OFF + t] = ((a0 + a1) + (a2 + a3)) * inv;
        } else if (t < 48) {
            // lin_h[i] = sum_d (Wq[i,hd]*bk[hd] + Wk[i,hd]*bq[hd])   (scaled)
            int idx = t - 36;
            int h = idx / 3, ii = idx % 3;
            const float* wq = &Wq[ii * PROJ + h * HD];
            const float* wk = &Wk[ii * PROJ + h * HD];
            const float* bqv = &bq[h * HD];
            const float* bkv = &bk[h * HD];
            float a0 = 0.f, a1 = 0.f;
#pragma unroll
            for (int d = 0; d < HD; d += 2) {
                a0 = fmaf(__ldg(&wq[d]),     __ldg(&bkv[d]),
                     fmaf(__ldg(&wk[d]),     __ldg(&bqv[d]), a0));
                a1 = fmaf(__ldg(&wq[d + 1]), __ldg(&bkv[d + 1]),
                     fmaf(__ldg(&wk[d + 1]), __ldg(&bqv[d + 1]), a1));
            }
            g_fold[LIN_OFF + idx] = (a0 + a1) * inv;
        } else if (t < 52) {
            // s0_h = bq_h . bk_h  (scaled)
            int h = t - 48;
            const float* bqv = &bq[h * HD];
            const float* bkv = &bk[h * HD];
            float a0 = 0.f, a1 = 0.f;
#pragma unroll
            for (int d = 0; d < HD; d += 2) {
                a0 = fmaf(__ldg(&bqv[d]),     __ldg(&bkv[d]),     a0);
                a1 = fmaf(__ldg(&bqv[d + 1]), __ldg(&bkv[d + 1]), a1);
            }
            g_fold[S0_OFF + h] = (a0 + a1) * inv;
        } else if (t >= 64 && t < 160) {
            int idx = t - 64;
            const float* src = (idx < HD) ? &bout[idx]
                             : (idx < 2 * HD) ? &gamma[idx - HD]
                             : &beta[idx - 2 * HD];
            g_fold[BOUT_OFF + idx] = __ldg(src);
        } else if (t == 192) {
            // int64 edge_index: node ids < 1e5 -> every odd 32-bit word is 0.
            int acc = 0;
#pragma unroll
            for (int k = 0; k < 32; k++) acc |= __ldg(&eraw[2 * k + 1]);
            g_is64 = (acc == 0);
        }
    }

    grid_bar(0);

    // ================= phase 1: per-edge scores + 16-wide scatter =================
    if (t < SCORE_SZ) sp[t] = g_fold[t];
    __syncthreads();
    const int is64 = g_is64;

    for (int p = gid; p < NE / 2; p += gsz) {
        int e0 = p * 2;
        int row0, col0, row1, col1;
        if (is64) {
            const longlong2* pr = reinterpret_cast<const longlong2*>(eraw);
            longlong2 rw = __ldg(&pr[e0 >> 1]);
            longlong2 cl = __ldg(&pr[(NE + e0) >> 1]);
            row0 = (int)rw.x; row1 = (int)rw.y;
            col0 = (int)cl.x; col1 = (int)cl.y;
        } else {
            const int2* pi = reinterpret_cast<const int2*>(eraw);
            int2 rw = __ldg(&pi[e0 >> 1]);
            int2 cl = __ldg(&pi[(NE + e0) >> 1]);
            row0 = rw.x; row1 = rw.y;
            col0 = cl.x; col1 = cl.y;
        }
        float4 pr0 = g_pos4[row0];
        float4 pc0 = g_pos4[col0];
        float4 pr1 = g_pos4[row1];
        float4 pc1 = g_pos4[col1];
        edge_compute(sp, col0, pr0, pc0);
        edge_compute(sp, col1, pr1, pc1);
    }

    grid_bar(1);

    // ================= phase 2: per-node u@B + LN + SiLU (quad, 2 nodes/thread) ====
    for (int i = t; i < U16 * HD; i += BLOCK_THREADS) sB[i] = g_fold[B_OFF + i];
    for (int i = t; i < 3 * HD; i += BLOCK_THREADS)  sEpi[i] = g_fold[BOUT_OFF + i];
    __syncthreads();

    const unsigned mask = 0xffffffffu;
    const int nitems = (NN / 2) * 4;                 // 200000; tail divisible by 32
    for (int item = gid; item < nitems; item += gsz) {
        int pair = item >> 2;
        int sub  = item & 3;
        int n0   = pair * 2;

        float s0[U16], s1[U16];
        const float4* p0 = reinterpret_cast<const float4*>(&g_seg[(size_t)n0 * U16]);
        const float4* p1 = reinterpret_cast<const float4*>(&g_seg[(size_t)(n0 + 1) * U16]);
#pragma unroll
        for (int k = 0; k < 4; k++) {
            float4 v = p0[k];
            s0[k*4+0]=v.x; s0[k*4+1]=v.y; s0[k*4+2]=v.z; s0[k*4+3]=v.w;
        }
#pragma unroll
        for (int k = 0; k < 4; k++) {
            float4 v = p1[k];
            s1[k*4+0]=v.x; s1[k*4+1]=v.y; s1[k*4+2]=v.z; s1[k*4+3]=v.w;
        }

        // all quad reads of this pair done -> re-zero our slice for next launch
        __syncwarp(mask);
        {
            float4 z = make_float4(0.f, 0.f, 0.f, 0.f);
            reinterpret_cast<float4*>(&g_seg[(size_t)n0 * U16])[sub] = z;
            reinterpret_cast<float4*>(&g_seg[(size_t)(n0 + 1) * U16])[sub] = z;
        }

        float rinv0 = 1.0f / fmaxf(s0[3] + s0[7] + s0[11] + s0[15], 1.0f);
        float rinv1 = 1.0f / fmaxf(s1[3] + s1[7] + s1[11] + s1[15], 1.0f);

        const int o0 = sub * 8;
        float y0[8], y1[8];
#pragma unroll
        for (int c = 0; c < 8; c++) { y0[c] = 0.f; y1[c] = 0.f; }
#pragma unroll
        for (int j = 0; j < U16; j++) {
            const float4* brow = reinterpret_cast<const float4*>(&sB[j * HD + o0]);
            float4 b0 = brow[0], b1 = brow[1];
            float a0 = s0[j], a1 = s1[j];
            y0[0]=fmaf(a0,b0.x,y0[0]); y0[1]=fmaf(a0,b0.y,y0[1]);
            y0[2]=fmaf(a0,b0.z,y0[2]); y0[3]=fmaf(a0,b0.w,y0[3]);
            y0[4]=fmaf(a0,b1.x,y0[4]); y0[5]=fmaf(a0,b1.y,y0[5]);
            y0[6]=fmaf(a0,b1.z,y0[6]); y0[7]=fmaf(a0,b1.w,y0[7]);
            y1[0]=fmaf(a1,b0.x,y1[0]); y1[1]=fmaf(a1,b0.y,y1[1]);
            y1[2]=fmaf(a1,b0.z,y1[2]); y1[3]=fmaf(a1,b0.w,y1[3]);
            y1[4]=fmaf(a1,b1.x,y1[4]); y1[5]=fmaf(a1,b1.y,y1[5]);
            y1[6]=fmaf(a1,b1.z,y1[6]); y1[7]=fmaf(a1,b1.w,y1[7]);
        }

        float sum0 = 0.f, sum1 = 0.f;
#pragma unroll
        for (int c = 0; c < 8; c++) {
            y0[c] = fmaf(y0[c], rinv0, sEpi[o0 + c]);
            y1[c] = fmaf(y1[c], rinv1, sEpi[o0 + c]);
            sum0 += y0[c]; sum1 += y1[c];
        }
        sum0 += __shfl_xor_sync(mask, sum0, 1);
        sum0 += __shfl_xor_sync(mask, sum0, 2);
        sum1 += __shfl_xor_sync(mask, sum1, 1);
        sum1 += __shfl_xor_sync(mask, sum1, 2);
        float mu0 = sum0 * (1.0f / 32.0f);
        float mu1 = sum1 * (1.0f / 32.0f);

        float sq0 = 0.f, sq1 = 0.f;
#pragma unroll
        for (int c = 0; c < 8; c++) {
            float d0 = y0[c] - mu0; sq0 = fmaf(d0, d0, sq0);
            float d1 = y1[c] - mu1; sq1 = fmaf(d1, d1, sq1);
        }
        sq0 += __shfl_xor_sync(mask, sq0, 1);
        sq0 += __shfl_xor_sync(mask, sq0, 2);
        sq1 += __shfl_xor_sync(mask, sq1, 1);
        sq1 += __shfl_xor_sync(mask, sq1, 2);
        float sf0 = rsqrtf(sq0 * (1.0f / 32.0f) + 1e-5f);
        float sf1 = rsqrtf(sq1 * (1.0f / 32.0f) + 1e-5f);

        float4* op0 = reinterpret_cast<float4*>(&out[(size_t)n0 * HD + o0]);
        float4* op1 = reinterpret_cast<float4*>(&out[(size_t)(n0 + 1) * HD + o0]);
#pragma unroll
        for (int k = 0; k < 2; k++) {
            float4 v0, v1;
            float* vp0 = &v0.x;
            float* vp1 = &v1.x;
#pragma unroll
            for (int c = 0; c < 4; c++) {
                int o = o0 + k * 4 + c;
                float g = sEpi[HD + o], bt = sEpi[2 * HD + o];
                float x0 = (y0[k*4+c] - mu0) * sf0 * g + bt;
                float x1 = (y1[k*4+c] - mu1) * sf1 * g + bt;
                vp0[c] = x0 / (1.0f + __expf(-x0));
                vp1[c] = x1 / (1.0f + __expf(-x1));
            }
            op0[k] = v0;
            op1[k] = v1;
        }
    }
}

// ---------------- launch ----------------
extern "C" void kernel_launch(void* const* d_in, const int* in_sizes, int n_in,
                              void* d_out, int out_size) {
    const float* pos   = (const float*)d_in[0];
    const int*   edge  = (const int*)d_in[1];
    const float* Wq    = (const float*)d_in[2];
    const float* bq    = (const float*)d_in[3];
    const float* Wk    = (const float*)d_in[4];
    const float* bk    = (const float*)d_in[5];
    const float* Wv    = (const float*)d_in[6];
    const float* bv    = (const float*)d_in[7];
    const float* Wout  = (const float*)d_in[8];
    const float* bout  = (const float*)d_in[9];
    const float* gamma = (const float*)d_in[10];
    const float* beta  = (const float*)d_in[11];
    float* out = (float*)d_out;

    fused_kernel<<<GRID_BLOCKS, BLOCK_THREADS>>>(pos, edge, Wq, bq, Wk, bk,
                                                 Wv, bv, Wout, bout, gamma, beta, out);
}

// round 8
// speedup vs baseline: 1.0580x; 1.0580x over previous
#include <cuda_runtime.h>

#define NN 100000   // nodes
#define NE 500000   // edges
#define NH 4        // heads
#define HD 32       // output width
#define PROJ 128
#define U16 16      // folded edge-feature width

// folded-parameter layout inside g_fold (floats)
#define A_OFF     0            // 4*3*3 = 36  quadratic form (pre-scaled 1/sqrt(32))
#define LIN_OFF   36           // 4*3  = 12
#define S0_OFF    48           // 4
#define SCORE_SZ  52
#define B_OFF     52           // 16*32 = 512
#define BOUT_OFF  564          // 32
#define GAMMA_OFF 596          // 32
#define BETA_OFF  628          // 32
#define FOLD_SZ   660

// ---------------- device scratch (no allocations allowed) ----------------
__device__ __align__(16) float g_seg[NN * U16];  // zeroed by pack_setup each launch
__device__ __align__(16) float4 g_pos4[NN];      // padded positions for 1-LDG gathers
__device__ __align__(16) float g_fold[FOLD_SZ];  // folded params
__device__ int   g_is64;                         // edge_index dtype flag

// ---------------- kernel 1: zero seg + pack positions + weight fold ----------------
__global__ void __launch_bounds__(256) pack_setup_kernel(
        const float* __restrict__ pos,
        const int* __restrict__ eraw,
        const float* __restrict__ Wq, const float* __restrict__ bq,
        const float* __restrict__ Wk, const float* __restrict__ bk,
        const float* __restrict__ Wv, const float* __restrict__ bv,
        const float* __restrict__ Wout, const float* __restrict__ bout,
        const float* __restrict__ gamma, const float* __restrict__ beta) {
    const int gid = blockIdx.x * blockDim.x + threadIdx.x;
    const int gsz = gridDim.x * blockDim.x;

    // zero the accumulator (grid-stride, v4)
    float4* s4 = reinterpret_cast<float4*>(g_seg);
    const int n4 = NN * U16 / 4;
    const float4 z = make_float4(0.f, 0.f, 0.f, 0.f);
    for (int j = gid; j < n4; j += gsz) s4[j] = z;

    // pack positions into float4
    for (int j = gid; j < NN; j += gsz)
        g_pos4[j] = make_float4(__ldg(&pos[j * 3 + 0]),
                                __ldg(&pos[j * 3 + 1]),
                                __ldg(&pos[j * 3 + 2]), 0.f);

    const int t = threadIdx.x;
    const float inv = 0.17677669529663687f;  // 1/sqrt(32)

    if (blockIdx.x < 2) {
        // ---- B fold: one thread per output, lane = o (coalesced Wout rows) ----
        // B[(h*4+ii)][o] = sum_d Wv[ii, h*32+d] * Wout[h*32+d, o]   (ii < 3)
        // B[(h*4+3)][o]  = sum_d bv[h*32+d]     * Wout[h*32+d, o]
        int idx = blockIdx.x * 256 + t;           // 0..511
        int j = idx >> 5, o = idx & 31;
        int h = j >> 2, ii = j & 3;
        const float* wsrc = (ii < 3) ? &Wv[ii * PROJ + h * HD] : &bv[h * HD];
        const float* wo   = &Wout[(size_t)h * HD * HD + o];
        float acc[8];
#pragma unroll
        for (int k = 0; k < 8; k++) acc[k] = 0.f;
#pragma unroll
        for (int d = 0; d < HD; d += 8) {
#pragma unroll
            for (int k = 0; k < 8; k++)
                acc[k] = fmaf(__ldg(&wsrc[d + k]), __ldg(&wo[(d + k) * HD]), acc[k]);
        }
        g_fold[B_OFF + idx] = ((acc[0] + acc[1]) + (acc[2] + acc[3]))
                            + ((acc[4] + acc[5]) + (acc[6] + acc[7]));
    } else if (blockIdx.x == 2) {
        if (t < NH * 9) {
            // A_h[i][j] = sum_d Wq[i, h*32+d] * Wk[j, h*32+d]   (scaled)
            int h = t / 9, ii = (t % 9) / 3, jj = t % 3;
            const float* wq = &Wq[ii * PROJ + h * HD];
            const float* wk = &Wk[jj * PROJ + h * HD];
            float acc[8];
#pragma unroll
            for (int k = 0; k < 8; k++) acc[k] = 0.f;
#pragma unroll
            for (int d = 0; d < HD; d += 8) {
#pragma unroll
                for (int k = 0; k < 8; k++)
                    acc[k] = fmaf(__ldg(&wq[d + k]), __ldg(&wk[d + k]), acc[k]);
            }
            g_fold[A_OFF + t] = (((acc[0] + acc[1]) + (acc[2] + acc[3]))
                               + ((acc[4] + acc[5]) + (acc[6] + acc[7]))) * inv;
        } else if (t < 48) {
            // lin_h[i] = sum_d (Wq[i,hd]*bk[hd] + Wk[i,hd]*bq[hd])   (scaled)
            int idx = t - 36;
            int h = idx / 3, ii = idx % 3;
            const float* wq = &Wq[ii * PROJ + h * HD];
            const float* wk = &Wk[ii * PROJ + h * HD];
            const float* bqv = &bq[h * HD];
            const float* bkv = &bk[h * HD];
            float a0 = 0.f, a1 = 0.f, a2 = 0.f, a3 = 0.f;
#pragma unroll
            for (int d = 0; d < HD; d += 2) {
                a0 = fmaf(__ldg(&wq[d]),     __ldg(&bkv[d]),     a0);
                a1 = fmaf(__ldg(&wk[d]),     __ldg(&bqv[d]),     a1);
                a2 = fmaf(__ldg(&wq[d + 1]), __ldg(&bkv[d + 1]), a2);
                a3 = fmaf(__ldg(&wk[d + 1]), __ldg(&bqv[d + 1]), a3);
            }
            g_fold[LIN_OFF + idx] = ((a0 + a1) + (a2 + a3)) * inv;
        } else if (t < 52) {
            // s0_h = bq_h . bk_h  (scaled)
            int h = t - 48;
            const float* bqv = &bq[h * HD];
            const float* bkv = &bk[h * HD];
            float a0 = 0.f, a1 = 0.f;
#pragma unroll
            for (int d = 0; d < HD; d += 2) {
                a0 = fmaf(__ldg(&bqv[d]),     __ldg(&bkv[d]),     a0);
                a1 = fmaf(__ldg(&bqv[d + 1]), __ldg(&bkv[d + 1]), a1);
            }
            g_fold[S0_OFF + h] = (a0 + a1) * inv;
        } else if (t >= 64 && t < 160) {
            // epilogue params: bout | gamma | beta
            int idx = t - 64;
            const float* src = (idx < HD) ? &bout[idx]
                             : (idx < 2 * HD) ? &gamma[idx - HD]
                             : &beta[idx - 2 * HD];
            g_fold[BOUT_OFF + idx] = __ldg(src);
        } else if (t == 192) {
            // int64 edge_index: node ids < 1e5 -> every odd 32-bit word is 0.
            int acc = 0;
#pragma unroll
            for (int k = 0; k < 32; k++) acc |= __ldg(&eraw[2 * k + 1]);
            g_is64 = (acc == 0);
        }
    }
}

// ---------------- kernel 2: per-edge scores + 16-wide scatter (2 edges/thread) ----------------
__device__ __forceinline__ void red_add_v4(float* p, float4 v) {
    asm volatile("red.global.add.v4.f32 [%0], {%1,%2,%3,%4};"
                 :: "l"(p), "f"(v.x), "f"(v.y), "f"(v.z), "f"(v.w)
                 : "memory");
}

__device__ __forceinline__ void edge_compute(const float* sp, int col, float4 pr, float4 pc) {
    float r[3] = { pr.x - pc.x, pr.y - pc.y, pr.z - pc.z };
    float s[NH];
    float mx = -1e30f;
#pragma unroll
    for (int h = 0; h < NH; h++) {
        float acc = sp[S0_OFF + h];
#pragma unroll
        for (int i = 0; i < 3; i++) {
            float t = sp[LIN_OFF + h * 3 + i];
#pragma unroll
            for (int j = 0; j < 3; j++)
                t = fmaf(sp[A_OFF + h * 9 + i * 3 + j], r[j], t);
            acc = fmaf(r[i], t, acc);
        }
        s[h] = acc;
        mx = fmaxf(mx, acc);
    }
    float a[NH], den = 0.f;
#pragma unroll
    for (int h = 0; h < NH; h++) { a[h] = __expf(s[h] - mx); den += a[h]; }
    float dinv = 1.0f / den;

    float* base = &g_seg[(size_t)col * U16];
#pragma unroll
    for (int h = 0; h < NH; h++) {
        float ah = a[h] * dinv;
        red_add_v4(base + h * 4, make_float4(ah * r[0], ah * r[1], ah * r[2], ah));
    }
}

__global__ void __launch_bounds__(256) edge_kernel(const int* __restrict__ eraw) {
    __shared__ float sp[SCORE_SZ];
    if (threadIdx.x < SCORE_SZ) sp[threadIdx.x] = g_fold[threadIdx.x];
    __syncthreads();

    int e0 = (blockIdx.x * blockDim.x + threadIdx.x) * 2;
    if (e0 >= NE) return;

    int row0, col0, row1, col1;
    if (g_is64) {
        const longlong2* pr = reinterpret_cast<const longlong2*>(eraw);
        longlong2 rw = __ldg(&pr[e0 >> 1]);            // rows e0, e0+1
        longlong2 cl = __ldg(&pr[(NE + e0) >> 1]);     // cols e0, e0+1
        row0 = (int)rw.x; row1 = (int)rw.y;
        col0 = (int)cl.x; col1 = (int)cl.y;
    } else {
        const int2* pi = reinterpret_cast<const int2*>(eraw);
        int2 rw = __ldg(&pi[e0 >> 1]);
        int2 cl = __ldg(&pi[(NE + e0) >> 1]);
        row0 = rw.x; row1 = rw.y;
        col0 = cl.x; col1 = cl.y;
    }

    float4 pr0 = g_pos4[row0];
    float4 pc0 = g_pos4[col0];
    float4 pr1 = g_pos4[row1];
    float4 pc1 = g_pos4[col1];

    edge_compute(sp, col0, pr0, pc0);
    edge_compute(sp, col1, pr1, pc1);
}

// ---------------- kernel 3: per-node u@B + LN + SiLU (quad-sub, 2 nodes/thread) ----------------
__global__ void __launch_bounds__(256) node_kernel(float* __restrict__ out) {
    __shared__ __align__(16) float sB[U16 * HD];   // 512 floats
    __shared__ __align__(16) float sEpi[3 * HD];   // bout | gamma | beta

    for (int i = threadIdx.x; i < U16 * HD; i += 256) sB[i] = g_fold[B_OFF + i];
    for (int i = threadIdx.x; i < 3 * HD; i += 256)  sEpi[i] = g_fold[BOUT_OFF + i];
    __syncthreads();

    int gt   = blockIdx.x * blockDim.x + threadIdx.x;
    int pair = gt >> 2;
    int sub  = gt & 3;
    int n0   = pair * 2;          // NN is even -> n0, n0+1 both valid when n0 < NN
    bool valid = (n0 < NN);
    unsigned mask = 0xffffffffu;

    float s0[U16], s1[U16];
    if (valid) {
        const float4* p0 = reinterpret_cast<const float4*>(&g_seg[(size_t)n0 * U16]);
        const float4* p1 = reinterpret_cast<const float4*>(&g_seg[(size_t)(n0 + 1) * U16]);
#pragma unroll
        for (int k = 0; k < 4; k++) {
            float4 v = p0[k];
            s0[k*4+0]=v.x; s0[k*4+1]=v.y; s0[k*4+2]=v.z; s0[k*4+3]=v.w;
        }
#pragma unroll
        for (int k = 0; k < 4; k++) {
            float4 v = p1[k];
            s1[k*4+0]=v.x; s1[k*4+1]=v.y; s1[k*4+2]=v.z; s1[k*4+3]=v.w;
        }
    } else {
#pragma unroll
        for (int k = 0; k < U16; k++) { s0[k] = 0.f; s1[k] = 0.f; }
    }

    float rinv0 = 1.0f / fmaxf(s0[3] + s0[7] + s0[11] + s0[15], 1.0f);
    float rinv1 = 1.0f / fmaxf(s1[3] + s1[7] + s1[11] + s1[15], 1.0f);

    const int o0 = sub * 8;
    float y0[8], y1[8];
#pragma unroll
    for (int c = 0; c < 8; c++) { y0[c] = 0.f; y1[c] = 0.f; }
#pragma unroll
    for (int j = 0; j < U16; j++) {
        const float4* brow = reinterpret_cast<const float4*>(&sB[j * HD + o0]);
        float4 b0 = brow[0], b1 = brow[1];
        float a0 = s0[j], a1 = s1[j];
        y0[0]=fmaf(a0,b0.x,y0[0]); y0[1]=fmaf(a0,b0.y,y0[1]);
        y0[2]=fmaf(a0,b0.z,y0[2]); y0[3]=fmaf(a0,b0.w,y0[3]);
        y0[4]=fmaf(a0,b1.x,y0[4]); y0[5]=fmaf(a0,b1.y,y0[5]);
        y0[6]=fmaf(a0,b1.z,y0[6]); y0[7]=fmaf(a0,b1.w,y0[7]);
        y1[0]=fmaf(a1,b0.x,y1[0]); y1[1]=fmaf(a1,b0.y,y1[1]);
        y1[2]=fmaf(a1,b0.z,y1[2]); y1[3]=fmaf(a1,b0.w,y1[3]);
        y1[4]=fmaf(a1,b1.x,y1[4]); y1[5]=fmaf(a1,b1.y,y1[5]);
        y1[6]=fmaf(a1,b1.z,y1[6]); y1[7]=fmaf(a1,b1.w,y1[7]);
    }

    float sum0 = 0.f, sum1 = 0.f;
#pragma unroll
    for (int c = 0; c < 8; c++) {
        y0[c] = fmaf(y0[c], rinv0, sEpi[o0 + c]);
        y1[c] = fmaf(y1[c], rinv1, sEpi[o0 + c]);
        sum0 += y0[c]; sum1 += y1[c];
    }
    sum0 += __shfl_xor_sync(mask, sum0, 1);
    sum0 += __shfl_xor_sync(mask, sum0, 2);
    sum1 += __shfl_xor_sync(mask, sum1, 1);
    sum1 += __shfl_xor_sync(mask, sum1, 2);
    float mu0 = sum0 * (1.0f / 32.0f);
    float mu1 = sum1 * (1.0f / 32.0f);

    float sq0 = 0.f, sq1 = 0.f;
#pragma unroll
    for (int c = 0; c < 8; c++) {
        float d0 = y0[c] - mu0; sq0 = fmaf(d0, d0, sq0);
        float d1 = y1[c] - mu1; sq1 = fmaf(d1, d1, sq1);
    }
    sq0 += __shfl_xor_sync(mask, sq0, 1);
    sq0 += __shfl_xor_sync(mask, sq0, 2);
    sq1 += __shfl_xor_sync(mask, sq1, 1);
    sq1 += __shfl_xor_sync(mask, sq1, 2);
    float sf0 = rsqrtf(sq0 * (1.0f / 32.0f) + 1e-5f);
    float sf1 = rsqrtf(sq1 * (1.0f / 32.0f) + 1e-5f);

    if (!valid) return;

    float4* op0 = reinterpret_cast<float4*>(&out[(size_t)n0 * HD + o0]);
    float4* op1 = reinterpret_cast<float4*>(&out[(size_t)(n0 + 1) * HD + o0]);
#pragma unroll
    for (int k = 0; k < 2; k++) {
        float4 v0, v1;
        float* vp0 = &v0.x;
        float* vp1 = &v1.x;
#pragma unroll
        for (int c = 0; c < 4; c++) {
            int o = o0 + k * 4 + c;
            float g = sEpi[HD + o], bt = sEpi[2 * HD + o];
            float x0 = (y0[k*4+c] - mu0) * sf0 * g + bt;
            float x1 = (y1[k*4+c] - mu1) * sf1 * g + bt;
            vp0[c] = x0 / (1.0f + __expf(-x0));
            vp1[c] = x1 / (1.0f + __expf(-x1));
        }
        op0[k] = v0;
        op1[k] = v1;
    }
}

// ---------------- launch ----------------
extern "C" void kernel_launch(void* const* d_in, const int* in_sizes, int n_in,
                              void* d_out, int out_size) {
    const float* pos   = (const float*)d_in[0];
    const int*   edge  = (const int*)d_in[1];
    const float* Wq    = (const float*)d_in[2];
    const float* bq    = (const float*)d_in[3];
    const float* Wk    = (const float*)d_in[4];
    const float* bk    = (const float*)d_in[5];
    const float* Wv    = (const float*)d_in[6];
    const float* bv    = (const float*)d_in[7];
    const float* Wout  = (const float*)d_in[8];
    const float* bout  = (const float*)d_in[9];
    const float* gamma = (const float*)d_in[10];
    const float* beta  = (const float*)d_in[11];
    float* out = (float*)d_out;

    pack_setup_kernel<<<608, 256>>>(pos, edge, Wq, bq, Wk, bk, Wv, bv,
                                    Wout, bout, gamma, beta);
    edge_kernel<<<(NE / 2 + 255) / 256, 256>>>(edge);
    node_kernel<<<(NN / 2 * 4 + 255) / 256, 256>>>(out);
}